// round 15
// baseline (speedup 1.0000x reference)
#include <cuda_runtime.h>
#include <cuda_bf16.h>
#include <math.h>
#include <stdint.h>

// ---------------------------------------------------------------- constants
#define TT     512
#define BB     128
#define DDIM   512
#define HH     64
#define NROWS  (TT * BB)          // 65536 independent (t,b) rows
#define NG     192                // 3 gates (i, g, o) x 64 qubits
#define EPSV   1e-5f
#define NTHR   512

// Arch-specific feature gate: tcgen05 exists only on sm_10xa targets.
#if defined(__CUDA_ARCH__) && (defined(__CUDA_ARCH_FEAT_SM103_ALL) || \
    defined(__CUDA_ARCH_FEAT_SM100_ALL) || defined(__CUDA_ARCH_SPECIFIC__))
#define HAS_TC 1
#endif

// dynamic SMEM layout:
//   A:       0 (hi 16KB) / 16384 (lo 16KB)
//   B:   32768 (hi 24KB) / 57344 (lo 24KB)
//   stage: 81920 (16KB: rows 0-63 of next x chunk, per-thread slots)
//   params/exchange: 98304 (12.8KB)
//   ctrl: 111104 (tmem ptr +0, mbar commit +8, mbar B-data +16)
#define OFF_A      0
#define OFF_B      32768
#define OFF_STG    81920
#define OFF_PAR    98304
#define OFF_CTRL   111104
#define SMEM_TOTAL 111168

// idesc: kind::f16, bf16 x bf16 -> f32, M=128, N=192
#define IDESC ((1u << 4) | (1u << 7) | (1u << 10) | ((NG / 8) << 17) | ((128 / 16) << 24))

#define B_HALF 24576u             // bytes per B half-tile (192 x 64 bf16)

// ---------------------------------------------------------------- scratch
__device__ __nv_bfloat16  g_B0hi[8 * NG * 64];   // W0: 8 K-chunks, SW128 swizzled
__device__ __nv_bfloat16  g_B0lo[8 * NG * 64];
__device__ __nv_bfloat16  g_B1hi[NG * 64];       // W1: 1 K-chunk
__device__ __nv_bfloat16  g_B1lo[NG * 64];

// ================================================================ prolog
__global__ void prep_w_kernel(const float* __restrict__ W0,
                              const float* __restrict__ W1) {
#ifdef HAS_TC
    int idx = blockIdx.x * blockDim.x + threadIdx.x;
    if (idx < 8 * NG * 16) {
        int c   = idx / (NG * 16);
        int rem = idx % (NG * 16);
        int n = rem / 16, k4 = rem % 16;
        float4 w4 = *(const float4*)(W0 + (size_t)(64 + n) * (DDIM + HH) + c * 64 + k4 * 4);
        uint32_t h01, h23, l01, l23;
        asm("cvt.rn.bf16x2.f32 %0, %1, %2;" : "=r"(h01) : "f"(w4.y), "f"(w4.x));
        asm("cvt.rn.bf16x2.f32 %0, %1, %2;" : "=r"(h23) : "f"(w4.w), "f"(w4.z));
        float hx = __uint_as_float(h01 << 16);
        float hy = __uint_as_float(h01 & 0xffff0000u);
        float hz = __uint_as_float(h23 << 16);
        float hw = __uint_as_float(h23 & 0xffff0000u);
        asm("cvt.rn.bf16x2.f32 %0, %1, %2;" : "=r"(l01) : "f"(w4.y - hy), "f"(w4.x - hx));
        asm("cvt.rn.bf16x2.f32 %0, %1, %2;" : "=r"(l23) : "f"(w4.w - hw), "f"(w4.z - hz));
        uint32_t boff = ((uint32_t)(n >> 3)) * 1024 + ((uint32_t)(n & 7)) * 128
                      + (uint32_t)k4 * 8;
        boff ^= ((boff >> 3) & 0x70);
        *(uint2*)((char*)g_B0hi + (size_t)c * 24576 + boff) = make_uint2(h01, h23);
        *(uint2*)((char*)g_B0lo + (size_t)c * 24576 + boff) = make_uint2(l01, l23);
    }
    if (idx < NG * 16) {
        int n = idx / 16, k4 = idx % 16;
        float4 w4 = *(const float4*)(W1 + (size_t)(64 + n) * (HH + HH) + k4 * 4);
        uint32_t h01, h23, l01, l23;
        asm("cvt.rn.bf16x2.f32 %0, %1, %2;" : "=r"(h01) : "f"(w4.y), "f"(w4.x));
        asm("cvt.rn.bf16x2.f32 %0, %1, %2;" : "=r"(h23) : "f"(w4.w), "f"(w4.z));
        float hx = __uint_as_float(h01 << 16);
        float hy = __uint_as_float(h01 & 0xffff0000u);
        float hz = __uint_as_float(h23 << 16);
        float hw = __uint_as_float(h23 & 0xffff0000u);
        asm("cvt.rn.bf16x2.f32 %0, %1, %2;" : "=r"(l01) : "f"(w4.y - hy), "f"(w4.x - hx));
        asm("cvt.rn.bf16x2.f32 %0, %1, %2;" : "=r"(l23) : "f"(w4.w - hw), "f"(w4.z - hz));
        uint32_t boff = ((uint32_t)(n >> 3)) * 1024 + ((uint32_t)(n & 7)) * 128
                      + (uint32_t)k4 * 8;
        boff ^= ((boff >> 3) & 0x70);
        *(uint2*)((char*)g_B1hi + boff) = make_uint2(h01, h23);
        *(uint2*)((char*)g_B1lo + boff) = make_uint2(l01, l23);
    }
#endif
}

// ================================================================ PTX helpers
#ifdef HAS_TC
typedef unsigned long long u64q;

static __device__ __forceinline__ uint32_t smem_u32(const void* p) {
    uint32_t a;
    asm("{ .reg .u64 t; cvta.to.shared.u64 t, %1; cvt.u32.u64 %0, t; }"
        : "=r"(a) : "l"(p));
    return a;
}
static __device__ __forceinline__ uint32_t elect1() {
    uint32_t p;
    asm volatile("{\n .reg .pred p;\n elect.sync _|p, 0xFFFFFFFF;\n selp.b32 %0,1,0,p;\n}"
                 : "=r"(p));
    return p;
}
static __device__ __forceinline__ uint64_t sdesc(uint32_t addr) {
    return (2ull << 61) | (1ull << 46) | (64ull << 32) | (1ull << 16)
         | ((uint64_t)(addr >> 4) & 0x3FFF);
}
static __device__ __forceinline__ void mma_bf16_ss(uint32_t d, uint64_t ad, uint64_t bd,
                                                   uint32_t idesc, bool accum) {
    uint32_t en = accum ? 1u : 0u;
    asm volatile(
        "{\n\t"
        ".reg .pred p;\n\t"
        "setp.ne.u32 p, %5, 0;\n\t"
        "tcgen05.mma.cta_group::1.kind::f16 [%0], %1, %2, %3, {%4, %4, %4, %4}, p;\n\t"
        "}"
        :: "r"(d), "l"(ad), "l"(bd), "r"(idesc), "r"(0u), "r"(en)
        : "memory");
}
static __device__ __forceinline__ void mbar_wait(uint32_t mbar, uint32_t parity) {
    uint32_t done;
    asm volatile(
        "{\n .reg .pred p;\n"
        " mbarrier.try_wait.parity.acquire.cta.shared::cta.b64 p, [%1], %2;\n"
        " selp.b32 %0, 1, 0, p;\n}"
        : "=r"(done) : "r"(mbar), "r"(parity) : "memory");
    if (!done) {
        asm volatile(
            "{\n .reg .pred P1;\n"
            "WL%=:\n"
            " mbarrier.try_wait.parity.acquire.cta.shared::cta.b64 P1, [%0], %1, 0x989680;\n"
            " @P1 bra.uni WD%=;\n"
            " bra.uni WL%=;\n"
            "WD%=:\n}"
            :: "r"(mbar), "r"(parity) : "memory");
    }
}
static __device__ __forceinline__ void bulk_g2s(uint32_t dst, const void* src,
                                                uint32_t bytes, uint32_t mbar) {
    asm volatile(
        "cp.async.bulk.shared::cta.global.mbarrier::complete_tx::bytes [%0], [%1], %2, [%3];"
        :: "r"(dst), "l"(src), "r"(bytes), "r"(mbar) : "memory");
}
static __device__ __forceinline__ void mbar_expect_tx(uint32_t mbar, uint32_t bytes) {
    asm volatile("mbarrier.arrive.expect_tx.shared.b64 _, [%0], %1;"
                 :: "r"(mbar), "r"(bytes) : "memory");
}
static __device__ __forceinline__ void gbar(int id) {
    asm volatile("bar.sync %0, %1;" :: "r"(id), "r"(128) : "memory");
}
#define CP_ASYNC16(dst, src) \
    asm volatile("cp.async.cg.shared.global [%0], [%1], 16;" :: "r"(dst), "l"(src) : "memory")
#define CP_COMMIT() asm volatile("cp.async.commit_group;" ::: "memory")
#define CP_WAIT0()  asm volatile("cp.async.wait_group 0;" ::: "memory")
#define TC_WAIT_LD() asm volatile("tcgen05.wait::ld.sync.aligned;" ::: "memory")
#define LDTM_X16(r, addr)                                              \
    asm volatile(                                                       \
        "tcgen05.ld.sync.aligned.32x32b.x16.b32 "                       \
        "{%0, %1, %2, %3, %4, %5, %6, %7, "                             \
        " %8, %9, %10, %11, %12, %13, %14, %15}, [%16];"                \
        : "=r"((r)[0]),  "=r"((r)[1]),  "=r"((r)[2]),  "=r"((r)[3]),    \
          "=r"((r)[4]),  "=r"((r)[5]),  "=r"((r)[6]),  "=r"((r)[7]),    \
          "=r"((r)[8]),  "=r"((r)[9]),  "=r"((r)[10]), "=r"((r)[11]),   \
          "=r"((r)[12]), "=r"((r)[13]), "=r"((r)[14]), "=r"((r)[15])    \
        : "r"(addr))

// ---- packed f32x2 (SASS FFMA2/FMUL2/FADD2; PTX-only pattern) ----
static __device__ __forceinline__ u64q pk(float a, float b) {
    u64q r; asm("mov.b64 %0, {%1, %2};" : "=l"(r) : "f"(a), "f"(b)); return r;
}
static __device__ __forceinline__ u64q pk2(float c) { return pk(c, c); }
static __device__ __forceinline__ void upk(u64q v, float& a, float& b) {
    asm("mov.b64 {%0, %1}, %2;" : "=f"(a), "=f"(b) : "l"(v));
}
static __device__ __forceinline__ u64q fma2(u64q a, u64q b, u64q c) {
    u64q r; asm("fma.rn.f32x2 %0, %1, %2, %3;" : "=l"(r) : "l"(a), "l"(b), "l"(c)); return r;
}
static __device__ __forceinline__ u64q mul2(u64q a, u64q b) {
    u64q r; asm("mul.rn.f32x2 %0, %1, %2;" : "=l"(r) : "l"(a), "l"(b)); return r;
}
static __device__ __forceinline__ u64q add2(u64q a, u64q b) {
    u64q r; asm("add.rn.f32x2 %0, %1, %2;" : "=l"(r) : "l"(a), "l"(b)); return r;
}
static __device__ __forceinline__ float frcp(float x) {
    float y; asm("rcp.approx.f32 %0, %1;" : "=f"(y) : "f"(x)); return y;
}
static __device__ __forceinline__ u64q psig2(u64q q) {
    u64q u = mul2(q, q);
    u64q p = fma2(u, pk2(-2.1638741e-6f), pk2(2.1358436e-5f));
    p = fma2(u, p, pk2(-2.1081349e-4f));
    p = fma2(u, p, pk2(2.0833333e-3f));
    p = fma2(u, p, pk2(-2.0833333e-2f));
    p = fma2(u, p, pk2(0.25f));
    return fma2(q, p, pk2(0.5f));
}
static __device__ __forceinline__ u64q ptanh2(u64q x) {
    u64q u = mul2(x, x);
    u64q n = fma2(add2(u, pk2(378.0f)), u, pk2(17325.0f));
    n = fma2(n, u, pk2(135135.0f));
    u64q d = fma2(pk2(28.0f), u, pk2(3150.0f));
    d = fma2(d, u, pk2(62370.0f));
    d = fma2(d, u, pk2(135135.0f));
    float d0, d1; upk(d, d0, d1);
    float r = frcp(d0 * d1);
    return mul2(mul2(mul2(x, n), pk(d1, d0)), pk2(r));
}

// ---------------------------------------------------------------- A convert
static __device__ __forceinline__ void conv_sts(float4 v, char* ah, char* al,
                                                uint32_t off) {
    uint32_t h01, h23, l01, l23;
    asm("cvt.rn.bf16x2.f32 %0, %1, %2;" : "=r"(h01) : "f"(v.y), "f"(v.x));
    asm("cvt.rn.bf16x2.f32 %0, %1, %2;" : "=r"(h23) : "f"(v.w), "f"(v.z));
    float hx = __uint_as_float(h01 << 16);
    float hy = __uint_as_float(h01 & 0xffff0000u);
    float hz = __uint_as_float(h23 << 16);
    float hw = __uint_as_float(h23 & 0xffff0000u);
    asm("cvt.rn.bf16x2.f32 %0, %1, %2;" : "=r"(l01) : "f"(v.y - hy), "f"(v.x - hx));
    asm("cvt.rn.bf16x2.f32 %0, %1, %2;" : "=r"(l23) : "f"(v.w - hw), "f"(v.z - hz));
    off ^= ((off >> 3) & 0x70);
    *(uint2*)(ah + off) = make_uint2(h01, h23);
    *(uint2*)(al + off) = make_uint2(l01, l23);
}

// ---------------------------------------------------------------- epilogue quarter
template <bool L0>
static __device__ __forceinline__ void epilogue_quarter(
    uint32_t tmem, const float* __restrict__ bt,
    const float* __restrict__ gm, const float* __restrict__ bet,
    volatile float* exg, volatile float* exs, volatile float* exss,
    char* ahi, char* alo, float* __restrict__ outp,
    float* __restrict__ hlast, float* __restrict__ clast,
    int q, int rl, int gid, int myrow)
{
    u64q hvp[8];
    float cs[16];
    uint32_t* ru = (uint32_t*)cs;
    const int colbase = q * 16;
    const bool tail = (myrow >= NROWS - BB);
    const int tb = myrow - (NROWS - BB);

#pragma unroll
    for (int g = 0; g < 3; g++) {
        LDTM_X16(ru, tmem + g * 64 + colbase);
        TC_WAIT_LD();
#pragma unroll
        for (int j = 0; j < 16; j++)
            cs[j] = __cosf(__uint_as_float(ru[j]) + bt[g * 64 + colbase + j]);

        u64q pr[8];
#pragma unroll
        for (int j = 0; j < 8; j++) pr[j] = pk(cs[j], cs[8 + j]);
#pragma unroll
        for (int j = 1; j < 8; j++) pr[j] = mul2(pr[j], pr[j - 1]);
        float c0t, c1t; upk(pr[7], c0t, c1t);
        u64q spl = pk(1.0f, c0t);
#pragma unroll
        for (int j = 0; j < 8; j++) pr[j] = mul2(pr[j], spl);

        exg[g * 512 + q * 128 + rl] = c0t * c1t;
        gbar(gid);
        if (q > 0) {
            float p = exg[g * 512 + rl];
            if (q >= 2) p *= exg[g * 512 + 128 + rl];
            if (q >= 3) p *= exg[g * 512 + 256 + rl];
            u64q pp = pk2(p);
#pragma unroll
            for (int j = 0; j < 8; j++) pr[j] = mul2(pr[j], pp);
        }

        if (g == 0) {
#pragma unroll
            for (int j = 0; j < 8; j++) hvp[j] = psig2(pr[j]);
        } else if (g == 1) {
#pragma unroll
            for (int j = 0; j < 8; j++)
                hvp[j] = mul2(hvp[j], ptanh2(psig2(pr[j])));     // c
            if (tail) {
                float h[16];
#pragma unroll
                for (int j = 0; j < 8; j++) upk(hvp[j], h[j], h[8 + j]);
                float4* cd = (float4*)(clast + (size_t)tb * HH) + q * 4;
#pragma unroll
                for (int j = 0; j < 4; j++)
                    cd[j] = make_float4(h[4*j], h[4*j+1], h[4*j+2], h[4*j+3]);
            }
        } else {
#pragma unroll
            for (int j = 0; j < 8; j++)
                hvp[j] = mul2(psig2(pr[j]), ptanh2(hvp[j]));     // h
        }
    }

    // layernorm: packed partial sums, one exchange round
    u64q ps = hvp[0], pss = mul2(hvp[0], hvp[0]);
#pragma unroll
    for (int j = 1; j < 8; j++) {
        ps  = add2(ps, hvp[j]);
        pss = fma2(hvp[j], hvp[j], pss);
    }
    float sa, sb, qa, qb;
    upk(ps, sa, sb); upk(pss, qa, qb);
    exs[q * 128 + rl]  = sa + sb;
    exss[q * 128 + rl] = qa + qb;
    gbar(gid);
    float mu  = (exs[rl] + exs[128 + rl] + exs[256 + rl] + exs[384 + rl]) * (1.0f / 64.0f);
    float eh2 = (exss[rl] + exss[128 + rl] + exss[256 + rl] + exss[384 + rl]) * (1.0f / 64.0f);
    float rinv = rsqrtf(fmaf(-mu, mu, eh2) + EPSV);

    u64q rp  = pk2(rinv);
    u64q mrp = pk2(-mu * rinv);
    float h[16];
#pragma unroll
    for (int j = 0; j < 8; j++) {
        u64q t   = fma2(hvp[j], rp, mrp);
        u64q gmp = pk(gm[colbase + j],  gm[colbase + 8 + j]);
        u64q bep = pk(bet[colbase + j], bet[colbase + 8 + j]);
        u64q r   = fma2(t, gmp, bep);
        upk(r, h[j], h[8 + j]);
    }

    if (L0) {
#pragma unroll
        for (int j8 = 0; j8 < 2; j8++) {
            uint32_t hw[4], lw[4];
#pragma unroll
            for (int p2 = 0; p2 < 4; p2++) {
                float v0 = h[j8 * 8 + p2 * 2], v1 = h[j8 * 8 + p2 * 2 + 1];
                asm("cvt.rn.bf16x2.f32 %0, %1, %2;" : "=r"(hw[p2]) : "f"(v1), "f"(v0));
                float h0f = __uint_as_float(hw[p2] << 16);
                float h1f = __uint_as_float(hw[p2] & 0xffff0000u);
                asm("cvt.rn.bf16x2.f32 %0, %1, %2;" : "=r"(lw[p2])
                    : "f"(v1 - h1f), "f"(v0 - h0f));
            }
            uint32_t off = (uint32_t)rl * 128 + (uint32_t)q * 32 + j8 * 16;
            off ^= ((off >> 3) & 0x70);
            *(uint4*)(ahi + off) = make_uint4(hw[0], hw[1], hw[2], hw[3]);
            *(uint4*)(alo + off) = make_uint4(lw[0], lw[1], lw[2], lw[3]);
        }
        if (tail) {
            float4* hd = (float4*)(hlast + (size_t)tb * HH) + q * 4;
#pragma unroll
            for (int j = 0; j < 4; j++)
                hd[j] = make_float4(h[4*j], h[4*j+1], h[4*j+2], h[4*j+3]);
        }
    } else {
        float4* od = (float4*)(outp + (size_t)myrow * HH) + q * 4;
#pragma unroll
        for (int j = 0; j < 4; j++)
            od[j] = make_float4(h[4*j], h[4*j+1], h[4*j+2], h[4*j+3]);
        if (tail) {
            float4* hd = (float4*)(hlast + (size_t)tb * HH) + q * 4;
#pragma unroll
            for (int j = 0; j < 4; j++)
                hd[j] = make_float4(h[4*j], h[4*j+1], h[4*j+2], h[4*j+3]);
        }
    }
}
#endif // HAS_TC

// ================================================================ fused kernel
__global__ void __launch_bounds__(NTHR, 2)
qlstm_fused_kernel(const float* __restrict__ x,
                   const float* __restrict__ W0raw,
                   const float* __restrict__ W1raw,
                   const __nv_bfloat16* __restrict__ B0hi_g,
                   const __nv_bfloat16* __restrict__ B0lo_g,
                   const __nv_bfloat16* __restrict__ B1hi_g,
                   const __nv_bfloat16* __restrict__ B1lo_g,
                   const float* __restrict__ b0, const float* __restrict__ th0,
                   const float* __restrict__ g0, const float* __restrict__ be0,
                   const float* __restrict__ b1, const float* __restrict__ th1,
                   const float* __restrict__ g1, const float* __restrict__ be1,
                   float* __restrict__ out,
                   float* __restrict__ h0last, float* __restrict__ c0last,
                   float* __restrict__ h1last, float* __restrict__ c1last)
{
    extern __shared__ __align__(1024) char smem[];
    const int tid = threadIdx.x, wid = tid >> 5, lane = tid & 31;
    const int q  = wid >> 2;                    // quarter 0..3 (16 gate cols)
    const int rl = (wid & 3) * 32 + lane;       // local row 0..127
    const int gid = 1 + (wid & 3);              // named-barrier id for row-group
    const int row0 = blockIdx.x * 128;
    const int myrow = row0 + rl;

    float* fp   = (float*)(smem + OFF_PAR);
    float* bt0  = fp;          // 192
    float* bt1  = fp + 192;    // 192
    float* gm0  = fp + 384;    // 64
    float* bet0 = fp + 448;
    float* gm1  = fp + 512;
    float* bet1 = fp + 576;
    float* exg  = fp + 640;    // 3 x 512 (per-gate exchange)
    float* exs  = fp + 2176;   // 512 (LN sum)
    float* exss = fp + 2688;   // 512 (LN sum of squares)

    if (tid < NG) {
        bt0[tid] = b0[64 + tid] + th0[64 + tid];
        bt1[tid] = b1[64 + tid] + th1[64 + tid];
    }
    if (tid >= 192 && tid < 256) {
        int i = tid - 192;
        gm0[i] = g0[i]; bet0[i] = be0[i];
        gm1[i] = g1[i]; bet1[i] = be1[i];
    }

#ifdef HAS_TC
    constexpr int NC = 8;
    const uint32_t sb  = smem_u32(smem);
    const uint32_t mb  = sb + OFF_CTRL + 8;     // MMA commit barrier
    const uint32_t mbB = sb + OFF_CTRL + 16;    // B-tile TMA data barrier
    if (wid == 0) {
        asm volatile("tcgen05.alloc.cta_group::1.sync.aligned.shared::cta.b32 [%0], %1;"
                     :: "r"(sb + OFF_CTRL), "r"(256u) : "memory");
        asm volatile("tcgen05.relinquish_alloc_permit.cta_group::1.sync.aligned;");
    }
    if (tid == 0) {
        asm volatile("mbarrier.init.shared.b64 [%0], %1;" :: "r"(mb),  "r"(1u) : "memory");
        asm volatile("mbarrier.init.shared.b64 [%0], %1;" :: "r"(mbB), "r"(1u) : "memory");
    }

    // preamble: stage rows 0-63 of chunk 0 (per-thread slots idx, idx+512)
    {
        const uint32_t stg = sb + OFF_STG;
#pragma unroll
        for (int j = 0; j < 2; j++) {
            int idx = tid + j * NTHR;            // 0..1023 -> rows 0..63
            int r = idx >> 4, s = idx & 15;
            CP_ASYNC16(stg + (uint32_t)idx * 16,
                       x + (size_t)(row0 + r) * DDIM + s * 4);
        }
        CP_COMMIT();
    }
    __syncthreads();
    uint32_t tmem;
    asm volatile("ld.shared.b32 %0, [%1];" : "=r"(tmem) : "r"(sb + OFF_CTRL));

    const uint64_t aHd = sdesc(sb + OFF_A);
    const uint64_t aLd = sdesc(sb + OFF_A + 16384);
    const uint64_t bHd = sdesc(sb + OFF_B);
    const uint64_t bLd = sdesc(sb + OFF_B + B_HALF);
    char* ah = smem + OFF_A;
    char* al = smem + OFF_A + 16384;
    const char* stgp = smem + OFF_STG;

    // ---------------- layer-0 K-chunk loop (staged x + TMA B) ----------------
    for (int c = 0; c < NC; c++) {
        if (c > 0) mbar_wait(mb, (c - 1) & 1);   // A & B buffers free

        if (tid == 0) {
            mbar_expect_tx(mbB, 2 * B_HALF);
            bulk_g2s(sb + OFF_B,          B0hi_g + (size_t)c * (NG * 64), B_HALF, mbB);
            bulk_g2s(sb + OFF_B + B_HALF, B0lo_g + (size_t)c * (NG * 64), B_HALF, mbB);
        }

        // rows 64-127: direct LDG issued first (latency overlaps staged half)
        float4 vd0, vd1;
        {
            int idx0 = tid + 2 * NTHR, idx1 = tid + 3 * NTHR;
            vd0 = *(const float4*)(x + (size_t)(row0 + (idx0 >> 4)) * DDIM
                                     + c * 64 + (idx0 & 15) * 4);
            vd1 = *(const float4*)(x + (size_t)(row0 + (idx1 >> 4)) * DDIM
                                     + c * 64 + (idx1 & 15) * 4);
        }
        // rows 0-63: consume own staged slots (cp.async group from last iter)
        CP_WAIT0();
#pragma unroll
        for (int j = 0; j < 2; j++) {
            int idx = tid + j * NTHR;
            int r = idx >> 4, s = idx & 15;
            float4 v = *(const float4*)(stgp + (uint32_t)idx * 16);
            conv_sts(v, ah, al, (uint32_t)r * 128 + (uint32_t)s * 8);
        }
        // rows 64-127: convert the direct loads
        {
            int idx0 = tid + 2 * NTHR, idx1 = tid + 3 * NTHR;
            conv_sts(vd0, ah, al, (uint32_t)(idx0 >> 4) * 128 + (uint32_t)(idx0 & 15) * 8);
            conv_sts(vd1, ah, al, (uint32_t)(idx1 >> 4) * 128 + (uint32_t)(idx1 & 15) * 8);
        }
        __syncthreads();                          // A tile complete (staged reads done)

        // prefetch rows 0-63 of chunk c+1 — overlaps MMA(c) + commit wait
        if (c + 1 < NC) {
            const uint32_t stg = sb + OFF_STG;
#pragma unroll
            for (int j = 0; j < 2; j++) {
                int idx = tid + j * NTHR;
                int r = idx >> 4, s = idx & 15;
                CP_ASYNC16(stg + (uint32_t)idx * 16,
                           x + (size_t)(row0 + r) * DDIM + (c + 1) * 64 + s * 4);
            }
            CP_COMMIT();
        }

        if (wid == 0 && elect1()) {
            mbar_wait(mbB, c & 1);                // B tile delivered
            asm volatile("fence.proxy.async.shared::cta;" ::: "memory");
#pragma unroll
            for (int ks = 0; ks < 4; ks++)
                mma_bf16_ss(tmem, aHd + ks * 2, bHd + ks * 2, IDESC, !(c == 0 && ks == 0));
#pragma unroll
            for (int ks = 0; ks < 4; ks++)
                mma_bf16_ss(tmem, aHd + ks * 2, bLd + ks * 2, IDESC, true);
#pragma unroll
            for (int ks = 0; ks < 4; ks++)
                mma_bf16_ss(tmem, aLd + ks * 2, bHd + ks * 2, IDESC, true);
            asm volatile(
                "tcgen05.commit.cta_group::1.mbarrier::arrive::one.shared::cluster.b64 [%0];"
                :: "r"(mb) : "memory");
        }
    }

    mbar_wait(mb, (NC - 1) & 1);
    asm volatile("tcgen05.fence::after_thread_sync;" ::: "memory");

    // B1 via bulk TMA — overlaps the whole epilogue-0
    if (tid == 0) {
        mbar_expect_tx(mbB, 2 * B_HALF);
        bulk_g2s(sb + OFF_B,          B1hi_g, B_HALF, mbB);
        bulk_g2s(sb + OFF_B + B_HALF, B1lo_g, B_HALF, mbB);
    }

    // ---------------- epilogue 0 (writes layer-1 A tile) ----------------
    epilogue_quarter<true>(tmem, bt0, gm0, bet0, exg, exs, exss, ah, al,
                           nullptr, h0last, c0last, q, rl, gid, myrow);

    asm volatile("tcgen05.fence::before_thread_sync;" ::: "memory");
    __syncthreads();

    // ---------------- layer-1 GEMM (K=64, reuse TMEM cols 0-191) ----------
    if (wid == 0 && elect1()) {
        mbar_wait(mbB, NC & 1);                   // B1 delivered (9th -> parity 0)
        asm volatile("tcgen05.fence::after_thread_sync;" ::: "memory");
        asm volatile("fence.proxy.async.shared::cta;" ::: "memory");
#pragma unroll
        for (int ks = 0; ks < 4; ks++)
            mma_bf16_ss(tmem, aHd + ks * 2, bHd + ks * 2, IDESC, ks != 0);
#pragma unroll
        for (int ks = 0; ks < 4; ks++)
            mma_bf16_ss(tmem, aHd + ks * 2, bLd + ks * 2, IDESC, true);
#pragma unroll
        for (int ks = 0; ks < 4; ks++)
            mma_bf16_ss(tmem, aLd + ks * 2, bHd + ks * 2, IDESC, true);
        asm volatile(
            "tcgen05.commit.cta_group::1.mbarrier::arrive::one.shared::cluster.b64 [%0];"
            :: "r"(mb) : "memory");
    }
    mbar_wait(mb, NC & 1);      // 9th commit completion -> parity 0
    asm volatile("tcgen05.fence::after_thread_sync;" ::: "memory");

    // ---------------- epilogue 1 (writes final output) ----------------
    epilogue_quarter<false>(tmem, bt1, gm1, bet1, exg, exs, exss, nullptr, nullptr,
                            out, h1last, c1last, q, rl, gid, myrow);

    asm volatile("tcgen05.fence::before_thread_sync;" ::: "memory");
    __syncthreads();
    if (wid == 0) {
        asm volatile("tcgen05.dealloc.cta_group::1.sync.aligned.b32 %0, %1;"
                     :: "r"(tmem), "r"(256u));
    }

#else  // ---------------- scalar fallback (correctness-only) ----------------
    float* xs = (float*)smem;                    // [128][64] fp32 (0..32KB)
    float* ws = (float*)(smem + 32768);          // [192][64] fp32 (32..80KB)
    const int colbase = q * 16;
    const bool tail = (myrow >= NROWS - BB);
    const int tb = myrow - (NROWS - BB);
    __syncthreads();

    float z[48];
#pragma unroll
    for (int i = 0; i < 48; i++) z[i] = 0.0f;

    for (int kt = 0; kt < 8; kt++) {
        __syncthreads();
        for (int i = tid; i < 128 * 16; i += NTHR) {
            int r = i >> 4, s = i & 15;
            *(float4*)&xs[r * 64 + s * 4] =
                *(const float4*)(x + (size_t)(row0 + r) * DDIM + kt * 64 + s * 4);
        }
        for (int i = tid; i < 192 * 16; i += NTHR) {
            int n = i >> 4, s = i & 15;
            *(float4*)&ws[n * 64 + s * 4] =
                *(const float4*)(W0raw + (size_t)(64 + n) * (DDIM + HH) + kt * 64 + s * 4);
        }
        __syncthreads();
        for (int g = 0; g < 3; g++)
            for (int j = 0; j < 16; j++) {
                int n = g * 64 + colbase + j;
                float acc = z[g * 16 + j];
                for (int k = 0; k < 64; k++)
                    acc = fmaf(xs[rl * 64 + k], ws[n * 64 + k], acc);
                z[g * 16 + j] = acc;
            }
    }

    for (int layer = 0; layer < 2; layer++) {
        const float* bt  = layer ? bt1  : bt0;
        const float* gm  = layer ? gm1  : gm0;
        const float* bet = layer ? bet1 : bet0;
        float* hl = layer ? h1last : h0last;
        float* cl = layer ? c1last : c0last;
        float hv[16];
        for (int g = 0; g < 3; g++) {
            float cs[16];
            for (int j = 0; j < 16; j++)
                cs[j] = cosf(z[g * 16 + j] + bt[g * 64 + colbase + j]);
            for (int j = 1; j < 16; j++) cs[j] *= cs[j - 1];
            exg[g * 512 + q * 128 + rl] = cs[15];
            __syncthreads();
            if (q > 0) {
                float p = exg[g * 512 + rl];
                if (q >= 2) p *= exg[g * 512 + 128 + rl];
                if (q >= 3) p *= exg[g * 512 + 256 + rl];
                for (int j = 0; j < 16; j++) cs[j] *= p;
            }
            __syncthreads();
            if (g == 0)      for (int j = 0; j < 16; j++) hv[j] = 1.0f / (1.0f + expf(-cs[j]));
            else if (g == 1) {
                for (int j = 0; j < 16; j++) hv[j] *= tanhf(1.0f / (1.0f + expf(-cs[j])));
                if (tail) for (int j = 0; j < 16; j++) cl[(size_t)tb * HH + colbase + j] = hv[j];
            } else           for (int j = 0; j < 16; j++) hv[j] = (1.0f / (1.0f + expf(-cs[j]))) * tanhf(hv[j]);
        }
        float s = 0.0f, ssq = 0.0f;
        for (int j = 0; j < 16; j++) { s += hv[j]; ssq += hv[j] * hv[j]; }
        exs[q * 128 + rl] = s;
        exss[q * 128 + rl] = ssq;
        __syncthreads();
        float mu  = (exs[rl] + exs[128 + rl] + exs[256 + rl] + exs[384 + rl]) * (1.0f / 64.0f);
        float eh2 = (exss[rl] + exss[128 + rl] + exss[256 + rl] + exss[384 + rl]) * (1.0f / 64.0f);
        float rinv = rsqrtf(eh2 - mu * mu + EPSV);
        for (int j = 0; j < 16; j++)
            hv[j] = (hv[j] - mu) * rinv * gm[colbase + j] + bet[colbase + j];
        __syncthreads();

        if (layer == 0) {
            for (int j = 0; j < 16; j++) xs[rl * 64 + colbase + j] = hv[j];
            __syncthreads();
            for (int i = tid; i < 192 * 16; i += NTHR) {
                int n = i >> 4, sdx = i & 15;
                *(float4*)&ws[n * 64 + sdx * 4] =
                    *(const float4*)(W1raw + (size_t)(64 + n) * (HH + HH) + sdx * 4);
            }
            __syncthreads();
            for (int g = 0; g < 3; g++)
                for (int j = 0; j < 16; j++) {
                    int n = g * 64 + colbase + j;
                    float acc = 0.0f;
                    for (int k = 0; k < 64; k++)
                        acc = fmaf(xs[rl * 64 + k], ws[n * 64 + k], acc);
                    z[g * 16 + j] = acc;
                }
            if (tail)
                for (int j = 0; j < 16; j++) hl[(size_t)tb * HH + colbase + j] = hv[j];
        } else {
            for (int j = 0; j < 16; j++) out[(size_t)myrow * HH + colbase + j] = hv[j];
            if (tail) for (int j = 0; j < 16; j++) hl[(size_t)tb * HH + colbase + j] = hv[j];
        }
        __syncthreads();
    }
#endif // HAS_TC
}

// ================================================================ launch
extern "C" void kernel_launch(void* const* d_in, const int* in_sizes, int n_in,
                              void* d_out, int out_size) {
    const float* inputs = (const float*)d_in[0];
    const float* W0  = (const float*)d_in[1];
    const float* b0  = (const float*)d_in[2];
    const float* th0 = (const float*)d_in[3];
    const float* g0  = (const float*)d_in[4];
    const float* be0 = (const float*)d_in[5];
    const float* W1  = (const float*)d_in[6];
    const float* b1  = (const float*)d_in[7];
    const float* th1 = (const float*)d_in[8];
    const float* g1  = (const float*)d_in[9];
    const float* be1 = (const float*)d_in[10];

    float* out = (float*)d_out;
    const size_t out_main = (size_t)NROWS * HH;
    float* h0last = out + out_main;
    float* c0last = h0last + BB * HH;
    float* h1last = c0last + BB * HH;
    float* c1last = h1last + BB * HH;

    __nv_bfloat16 *b0hi, *b0lo, *b1hi, *b1lo;
    cudaGetSymbolAddress((void**)&b0hi, g_B0hi);
    cudaGetSymbolAddress((void**)&b0lo, g_B0lo);
    cudaGetSymbolAddress((void**)&b1hi, g_B1hi);
    cudaGetSymbolAddress((void**)&b1lo, g_B1lo);

    cudaFuncSetAttribute((const void*)qlstm_fused_kernel,
                         cudaFuncAttributeMaxDynamicSharedMemorySize, SMEM_TOTAL);

    prep_w_kernel<<<(8 * NG * 16 + 255) / 256, 256>>>(W0, W1);

    qlstm_fused_kernel<<<NROWS / 128, NTHR, SMEM_TOTAL>>>(
        inputs, W0, W1, b0hi, b0lo, b1hi, b1lo,
        b0, th0, g0, be0, b1, th1, g1, be1,
        out, h0last, c0last, h1last, c1last);
}